// round 7
// baseline (speedup 1.0000x reference)
#include <cuda_runtime.h>
#include <cuda_bf16.h>
#include <cstdint>
#include <math.h>

#define N_NODES   8192
#define N_EDGES   16384
#define N_GRAPHS  256
#define N_STEMS   2048
#define N_JBONDS  1024
#define DIM       64
#define NUM_FEAT  14
#define NUM_OUT   105

#define Y_COLS    4224     // 65 chunks * 64 + pad to 66*64; chunk 64 = B2 term
#define Y_USED    4160

// ---------------- scratch (device globals; no allocations allowed) ----------------
__device__ __nv_bfloat16 g_w2y[Y_COLS * 64];        // B for y-GEMM: [(k,o) row][i] bf16
__device__ __nv_bfloat16 g_y[(size_t)N_NODES * Y_COLS]; // per-node y (bf16, ~69 MB)
__device__ float g_h1f[N_EDGES * DIM];              // edge-net hidden (fp32)
__device__ float g_rt[64 * 64];                     // conv_root^T [o][i] fp32
__device__ float g_wihT[192 * 64];                  // gru_w_ih^T [o][i] fp32
__device__ float g_whhT[192 * 64];                  // gru_w_hh^T [o][i] fp32
__device__ float g_h[N_NODES * DIM];                // node state
__device__ float g_agg[N_NODES * DIM];              // scatter accumulator
__device__ float g_deg[N_NODES];                    // becomes 1/max(deg,1)
__device__ float g_q[DIM];

__device__ __forceinline__ float lrelu(float v) { return v > 0.f ? v : 0.01f * v; }
__device__ __forceinline__ float sigm(float v)  { return 1.f / (1.f + expf(-v)); }

__device__ __forceinline__ void mma_bf16(float* c, const uint32_t* a, const uint32_t* b) {
    asm volatile(
        "mma.sync.aligned.m16n8k16.row.col.f32.bf16.bf16.f32 "
        "{%0,%1,%2,%3}, {%4,%5,%6,%7}, {%8,%9}, {%0,%1,%2,%3};"
        : "+f"(c[0]), "+f"(c[1]), "+f"(c[2]), "+f"(c[3])
        : "r"(a[0]), "r"(a[1]), "r"(a[2]), "r"(a[3]), "r"(b[0]), "r"(b[1]));
}

__device__ __forceinline__ uint32_t f2tf32(float f) {
    uint32_t r;
    asm("cvt.rna.tf32.f32 %0, %1;" : "=r"(r) : "f"(f));
    return r;
}

__device__ __forceinline__ void mma_tf32(float* c, const uint32_t* a, const uint32_t* b) {
    asm volatile(
        "mma.sync.aligned.m16n8k8.row.col.f32.tf32.tf32.f32 "
        "{%0,%1,%2,%3}, {%4,%5,%6,%7}, {%8,%9}, {%0,%1,%2,%3};"
        : "+f"(c[0]), "+f"(c[1]), "+f"(c[2]), "+f"(c[3])
        : "r"(a[0]), "r"(a[1]), "r"(a[2]), "r"(a[3]), "r"(b[0]), "r"(b[1]));
}

// ---------------- degree / init ----------------
__global__ void zero_deg_kernel() {
    g_deg[blockIdx.x * 256 + threadIdx.x] = 0.f;
}
__global__ void deg_kernel(const int* __restrict__ dst) {
    int e = blockIdx.x * 256 + threadIdx.x;
    if (e < N_EDGES) atomicAdd(&g_deg[dst[e]], 1.0f);
}
__global__ void invdeg_kernel() {
    int i = blockIdx.x * 256 + threadIdx.x;
    g_deg[i] = 1.0f / fmaxf(g_deg[i], 1.0f);
}
__global__ void zero_agg_kernel() {
    int i = blockIdx.x * 256 + threadIdx.x;
    ((float4*)g_agg)[i] = make_float4(0.f, 0.f, 0.f, 0.f);
}

// ---------------- lin0: h = lrelu(x @ W + b) ----------------
__global__ void lin0_kernel(const float* __restrict__ x,
                            const float* __restrict__ W,
                            const float* __restrict__ b) {
    int tid = blockIdx.x * 256 + threadIdx.x;
    int n = tid >> 6, o = tid & 63;
    float acc = b[o];
#pragma unroll
    for (int i = 0; i < NUM_FEAT; i++) acc += x[n * NUM_FEAT + i] * W[i * DIM + o];
    g_h[(size_t)n * DIM + o] = lrelu(acc);
}

// ---------------- edge net hidden: h1 = lrelu(ea @ W1 + b1), fp32 ----------------
__global__ void h1_kernel(const float* __restrict__ ea,
                          const float* __restrict__ W1,
                          const float* __restrict__ b1) {
    int tid = blockIdx.x * 256 + threadIdx.x;
    int e = tid >> 6, k = tid & 63;
    float acc = b1[k];
#pragma unroll
    for (int i = 0; i < 4; i++) acc += ea[e * 4 + i] * W1[i * DIM + k];
    g_h1f[(size_t)e * DIM + k] = lrelu(acc);
}

// ------- W2 rearrange for y-GEMM: g_w2y[k*64+o][i] = W2[k][i*64+o]; row 4096+o = B2
__global__ void w2y_kernel(const float* __restrict__ W2, const float* __restrict__ b2) {
    int idx = blockIdx.x * 256 + threadIdx.x;   // over Y_COLS*64
    if (idx >= Y_COLS * 64) return;
    int r = idx >> 6, i = idx & 63;
    float v;
    if (r < 4096) {
        int k = r >> 6, o = r & 63;
        v = W2[k * 4096 + i * 64 + o];
    } else if (r < Y_USED) {
        int o = r - 4096;
        v = b2[i * 64 + o];
    } else {
        v = 0.f;
    }
    g_w2y[r * 64 + i] = __float2bfloat16(v);
}

// ---------------- GRU/root weights -> transposed fp32 ----------------
__global__ void prep_weights_kernel(const float* __restrict__ R,
                                    const float* __restrict__ Wih,
                                    const float* __restrict__ Whh) {
    int i = blockIdx.x * 256 + threadIdx.x;     // 0 .. 28671
    if (i < 4096) {
        int o = i >> 6, k = i & 63;
        g_rt[o * 64 + k] = R[k * 64 + o];
    } else if (i < 4096 + 12288) {
        int j = i - 4096;
        int o = j >> 6, k = j & 63;
        g_wihT[o * 64 + k] = Wih[k * 192 + o];
    } else {
        int j = i - 4096 - 12288;
        int o = j >> 6, k = j & 63;
        g_whhT[o * 64 + k] = Whh[k * 192 + o];
    }
}

// ---------------- y = h @ W2y : M=8192, N=4224, K=64 (bf16 mma, fp32 acc) ----------
__global__ __launch_bounds__(256) void y_gemm_tc() {
    __shared__ __nv_bfloat16 As[128][72];
    __shared__ __nv_bfloat16 Bs[128][72];
    int bm = blockIdx.y * 128, bn = blockIdx.x * 128;
    int tid = threadIdx.x;

    // A: g_h fp32 -> bf16 smem (128 rows x 64)
#pragma unroll
    for (int p = 0; p < 8; p++) {
        int idx = tid + p * 256;                 // 2048 tasks: 128 rows x 16 segs
        int row = idx >> 4, c4 = (idx & 15) * 4;
        float4 v = *(const float4*)&g_h[(size_t)(bm + row) * 64 + c4];
        __nv_bfloat162 p0 = __floats2bfloat162_rn(v.x, v.y);
        __nv_bfloat162 p1 = __floats2bfloat162_rn(v.z, v.w);
        uint2 u; u.x = *(uint32_t*)&p0; u.y = *(uint32_t*)&p1;
        *(uint2*)&As[row][c4] = u;
    }
    // B: g_w2y bf16 rows
#pragma unroll
    for (int p = 0; p < 4; p++) {
        int idx = tid + p * 256;                 // 1024 tasks: 128 rows x 8 segs
        int row = idx >> 3, c8 = (idx & 7) * 8;
        *(uint4*)&Bs[row][c8] = *(const uint4*)&g_w2y[(size_t)(bn + row) * 64 + c8];
    }
    __syncthreads();

    int w = tid >> 5, lane = tid & 31;
    int wm = (w >> 2) * 64, wn = (w & 3) * 32;
    int g = lane >> 2, t4 = lane & 3;

    float c[4][4][4];
#pragma unroll
    for (int mi = 0; mi < 4; mi++)
#pragma unroll
        for (int ni = 0; ni < 4; ni++)
#pragma unroll
            for (int r = 0; r < 4; r++) c[mi][ni][r] = 0.f;

#pragma unroll
    for (int ks = 0; ks < 4; ks++) {
        int k0 = ks * 16;
        uint32_t a[4][4], b[4][2];
#pragma unroll
        for (int mi = 0; mi < 4; mi++) {
            int r0 = wm + mi * 16 + g;
            a[mi][0] = *(const uint32_t*)&As[r0][k0 + 2 * t4];
            a[mi][1] = *(const uint32_t*)&As[r0 + 8][k0 + 2 * t4];
            a[mi][2] = *(const uint32_t*)&As[r0][k0 + 2 * t4 + 8];
            a[mi][3] = *(const uint32_t*)&As[r0 + 8][k0 + 2 * t4 + 8];
        }
#pragma unroll
        for (int ni = 0; ni < 4; ni++) {
            int nr = wn + ni * 8 + g;
            b[ni][0] = *(const uint32_t*)&Bs[nr][k0 + 2 * t4];
            b[ni][1] = *(const uint32_t*)&Bs[nr][k0 + 2 * t4 + 8];
        }
#pragma unroll
        for (int mi = 0; mi < 4; mi++)
#pragma unroll
            for (int ni = 0; ni < 4; ni++)
                mma_bf16(c[mi][ni], a[mi], b[ni]);
    }

#pragma unroll
    for (int mi = 0; mi < 4; mi++) {
        int row0 = bm + wm + mi * 16 + g;
#pragma unroll
        for (int ni = 0; ni < 4; ni++) {
            int n = bn + wn + ni * 8 + 2 * t4;
            __nv_bfloat162 v0 = __floats2bfloat162_rn(c[mi][ni][0], c[mi][ni][1]);
            __nv_bfloat162 v1 = __floats2bfloat162_rn(c[mi][ni][2], c[mi][ni][3]);
            *reinterpret_cast<__nv_bfloat162*>(&g_y[(size_t)row0 * Y_COLS + n]) = v0;
            *reinterpret_cast<__nv_bfloat162*>(&g_y[(size_t)(row0 + 8) * Y_COLS + n]) = v1;
        }
    }
}

// ---------------- msg: agg[dst] += [h1_e,1] @ y[src]   (16 edges/block) ------------
__global__ __launch_bounds__(256) void msg_y_kernel(const int* __restrict__ src,
                                                    const int* __restrict__ dst) {
    __shared__ float h1s[16][68];
    __shared__ int ssm[16], dsm[16];
    int tid = threadIdx.x;
    int e0 = blockIdx.x * 16;
    if (tid < 16) {
        ssm[tid] = src[e0 + tid];
        dsm[tid] = dst[e0 + tid];
    }
    {
        int row = tid >> 4, seg = tid & 15;      // 256 tasks = 16 x 16 float4
        float4 v = *(const float4*)&g_h1f[(size_t)(e0 + row) * 64 + seg * 4];
        *(float4*)&h1s[row][seg * 4] = v;
    }
    __syncthreads();

    int slot = tid >> 4, t16 = tid & 15;
    const __nv_bfloat16* yrow = g_y + (size_t)ssm[slot] * Y_COLS;
    const uint2* yp = reinterpret_cast<const uint2*>(yrow + t16 * 4);

    // bias chunk (k=64, coefficient 1.0)
    float4 acc;
    {
        uint2 raw = yp[64 * 16];
        float2 w01 = __bfloat1622float2(*reinterpret_cast<__nv_bfloat162*>(&raw.x));
        float2 w23 = __bfloat1622float2(*reinterpret_cast<__nv_bfloat162*>(&raw.y));
        acc = make_float4(w01.x, w01.y, w23.x, w23.y);
    }
#pragma unroll 8
    for (int k = 0; k < 64; k++) {
        float hv = h1s[slot][k];
        uint2 raw = yp[k * 16];                  // y[src][k*64 + t16*4 ..]
        float2 w01 = __bfloat1622float2(*reinterpret_cast<__nv_bfloat162*>(&raw.x));
        float2 w23 = __bfloat1622float2(*reinterpret_cast<__nv_bfloat162*>(&raw.y));
        acc.x += hv * w01.x; acc.y += hv * w01.y;
        acc.z += hv * w23.x; acc.w += hv * w23.y;
    }
    float* ap = &g_agg[(size_t)dsm[slot] * 64 + t16 * 4];
    atomicAdd(ap + 0, acc.x); atomicAdd(ap + 1, acc.y);
    atomicAdd(ap + 2, acc.z); atomicAdd(ap + 3, acc.w);
}

// ---------------- tf32 tensor-core NNConv epilogue + GRU (64 nodes/block) ----------
__global__ __launch_bounds__(256) void node_update_tc(
    const float* __restrict__ cbias,
    const float* __restrict__ bih, const float* __restrict__ bhh) {
    __shared__ float hsm[64][68];
    __shared__ float msm[64][68];
    int n0 = blockIdx.x * 64;
    int tid = threadIdx.x;

#pragma unroll
    for (int i = 0; i < 4; i++) {
        int idx = tid + i * 256;
        int row = idx >> 4, c4 = (idx & 15) * 4;
        *(float4*)&hsm[row][c4] = *(const float4*)&g_h[(size_t)(n0 + row) * 64 + c4];
    }
    __syncthreads();

    int w = tid >> 5, lane = tid & 31;
    int g = lane >> 2, t4 = lane & 3;
    int c0 = w * 8 + 2 * t4;

    float accB[4][4] = {};
#pragma unroll
    for (int ks = 0; ks < 8; ks++) {
        int k0 = ks * 8;
        uint32_t rb[2];
        int nrow = w * 8 + g;
        rb[0] = f2tf32(g_rt[nrow * 64 + k0 + t4]);
        rb[1] = f2tf32(g_rt[nrow * 64 + k0 + t4 + 4]);
#pragma unroll
        for (int mt = 0; mt < 4; mt++) {
            int r0 = mt * 16 + g;
            uint32_t a[4];
            a[0] = f2tf32(hsm[r0][k0 + t4]);
            a[1] = f2tf32(hsm[r0 + 8][k0 + t4]);
            a[2] = f2tf32(hsm[r0][k0 + t4 + 4]);
            a[3] = f2tf32(hsm[r0 + 8][k0 + t4 + 4]);
            mma_tf32(accB[mt], a, rb);
        }
    }
    {
        float2 cb = *(const float2*)&cbias[c0];
#pragma unroll
        for (int mt = 0; mt < 4; mt++) {
#pragma unroll
            for (int half = 0; half < 2; half++) {
                int row = mt * 16 + g + half * 8;
                int node = n0 + row;
                float inv = g_deg[node];
                float2 ag = *(float2*)&g_agg[(size_t)node * 64 + c0];
                *(float2*)&g_agg[(size_t)node * 64 + c0] = make_float2(0.f, 0.f);
                msm[row][c0]     = lrelu(ag.x * inv + accB[mt][half * 2 + 0] + cb.x);
                msm[row][c0 + 1] = lrelu(ag.y * inv + accB[mt][half * 2 + 1] + cb.y);
            }
        }
    }
    __syncthreads();

    float accI[4][3][4] = {};
    float accH[4][3][4] = {};
#pragma unroll
    for (int ks = 0; ks < 8; ks++) {
        int k0 = ks * 8;
        uint32_t bi[3][2], bh[3][2];
#pragma unroll
        for (int j = 0; j < 3; j++) {
            int nrow = j * 64 + w * 8 + g;
            bi[j][0] = f2tf32(g_wihT[nrow * 64 + k0 + t4]);
            bi[j][1] = f2tf32(g_wihT[nrow * 64 + k0 + t4 + 4]);
            bh[j][0] = f2tf32(g_whhT[nrow * 64 + k0 + t4]);
            bh[j][1] = f2tf32(g_whhT[nrow * 64 + k0 + t4 + 4]);
        }
#pragma unroll
        for (int mt = 0; mt < 4; mt++) {
            int r0 = mt * 16 + g;
            uint32_t am[4], ah[4];
            am[0] = f2tf32(msm[r0][k0 + t4]);
            am[1] = f2tf32(msm[r0 + 8][k0 + t4]);
            am[2] = f2tf32(msm[r0][k0 + t4 + 4]);
            am[3] = f2tf32(msm[r0 + 8][k0 + t4 + 4]);
            ah[0] = f2tf32(hsm[r0][k0 + t4]);
            ah[1] = f2tf32(hsm[r0 + 8][k0 + t4]);
            ah[2] = f2tf32(hsm[r0][k0 + t4 + 4]);
            ah[3] = f2tf32(hsm[r0 + 8][k0 + t4 + 4]);
#pragma unroll
            for (int j = 0; j < 3; j++) {
                mma_tf32(accI[mt][j], am, bi[j]);
                mma_tf32(accH[mt][j], ah, bh[j]);
            }
        }
    }

    float2 b_ir = *(const float2*)&bih[c0];
    float2 b_iz = *(const float2*)&bih[64 + c0];
    float2 b_in = *(const float2*)&bih[128 + c0];
    float2 b_hr = *(const float2*)&bhh[c0];
    float2 b_hz = *(const float2*)&bhh[64 + c0];
    float2 b_hn = *(const float2*)&bhh[128 + c0];
#pragma unroll
    for (int mt = 0; mt < 4; mt++) {
#pragma unroll
        for (int half = 0; half < 2; half++) {
            int row = mt * 16 + g + half * 8;
            int node = n0 + row;
            int o = half * 2;
            float2 hold = make_float2(hsm[row][c0], hsm[row][c0 + 1]);
            float rx = sigm(accI[mt][0][o] + b_ir.x + accH[mt][0][o] + b_hr.x);
            float zx = sigm(accI[mt][1][o] + b_iz.x + accH[mt][1][o] + b_hz.x);
            float nx = tanhf(accI[mt][2][o] + b_in.x + rx * (accH[mt][2][o] + b_hn.x));
            float ry = sigm(accI[mt][0][o + 1] + b_ir.y + accH[mt][0][o + 1] + b_hr.y);
            float zy = sigm(accI[mt][1][o + 1] + b_iz.y + accH[mt][1][o + 1] + b_hz.y);
            float ny = tanhf(accI[mt][2][o + 1] + b_in.y + ry * (accH[mt][2][o + 1] + b_hn.y));
            float2 hn;
            hn.x = (1.f - zx) * nx + zx * hold.x;
            hn.y = (1.f - zy) * ny + zy * hold.y;
            *(float2*)&g_h[(size_t)node * 64 + c0] = hn;
        }
    }
}

// ---------------- stem head ----------------
__global__ __launch_bounds__(128) void stem_kernel(const int* __restrict__ idx,
                                                   const float* __restrict__ W1, const float* __restrict__ b1,
                                                   const float* __restrict__ W2, const float* __restrict__ b2,
                                                   float* __restrict__ outp) {
    __shared__ float row[64], hid[64];
    int s = blockIdx.x, t = threadIdx.x;
    int atom = idx[s];
    if (t < 64) row[t] = g_h[(size_t)atom * 64 + t];
    __syncthreads();
    if (t < 64) {
        float acc = b1[t];
#pragma unroll
        for (int i = 0; i < 64; i++) acc += row[i] * W1[i * 64 + t];
        hid[t] = lrelu(acc);
    }
    __syncthreads();
    for (int o = t; o < NUM_OUT; o += 128) {
        float acc = b2[o];
#pragma unroll
        for (int i = 0; i < 64; i++) acc += hid[i] * W2[i * NUM_OUT + o];
        outp[512 + (size_t)s * NUM_OUT + o] = acc;
    }
}

// ---------------- jbond head ----------------
__global__ __launch_bounds__(128) void jbond_kernel(const int* __restrict__ idx,
                                                    const float* __restrict__ W1, const float* __restrict__ b1,
                                                    const float* __restrict__ w2, const float* __restrict__ b2,
                                                    float* __restrict__ outp) {
    __shared__ float row[2][64];
    __shared__ float warpsum[4];
    int jb = blockIdx.x, t = threadIdx.x;
    int a = t >> 6, tt = t & 63;
    int atom = idx[jb * 2 + a];
    row[a][tt] = g_h[(size_t)atom * 64 + tt];
    __syncthreads();
    float acc = b1[tt];
#pragma unroll
    for (int i = 0; i < 64; i++) acc += row[a][i] * W1[i * 64 + tt];
    float p = lrelu(acc) * w2[tt];
#pragma unroll
    for (int off = 16; off; off >>= 1) p += __shfl_xor_sync(0xffffffffu, p, off);
    if ((t & 31) == 0) warpsum[t >> 5] = p;
    __syncthreads();
    if (t == 0) {
        float p0 = warpsum[0] + warpsum[1] + b2[0];
        float p1 = warpsum[2] + warpsum[3] + b2[0];
        outp[512 + (size_t)N_STEMS * NUM_OUT + jb] = 0.5f * (p0 + p1);
    }
}

// ---------------- Set2Set q (bias-only; identical for all graphs) ----------------
__global__ void s2s_q_kernel(const float* __restrict__ bih, const float* __restrict__ bhh) {
    int d = threadIdx.x;
    float bi = bih[d]       + bhh[d];
    float bg = bih[128 + d] + bhh[128 + d];
    float bo = bih[192 + d] + bhh[192 + d];
    float c = sigm(bi) * tanhf(bg);
    g_q[d] = sigm(bo) * tanhf(c);
}

// ---------------- per-graph attention pool + lin_out ----------------
__global__ __launch_bounds__(128) void pool_kernel(const int* __restrict__ batch,
                                                   const float* __restrict__ W, const float* __restrict__ bias,
                                                   float* __restrict__ outp) {
    __shared__ int s_lo, s_hi;
    __shared__ float s_max[4], s_ws[4], s_pool[4][64], s_r[64];
    int b = blockIdx.x, t = threadIdx.x;
    if (t == 0) {
        int lo = 0, hi = N_NODES;
        while (lo < hi) { int m = (lo + hi) >> 1; if (batch[m] < b) lo = m + 1; else hi = m; }
        s_lo = lo;
        int lo2 = lo, hi2 = N_NODES;
        while (lo2 < hi2) { int m = (lo2 + hi2) >> 1; if (batch[m] < b + 1) lo2 = m + 1; else hi2 = m; }
        s_hi = lo2;
    }
    __syncthreads();
    int lo = s_lo, hi = s_hi;
    int warp = t >> 5, lane = t & 31;
    float q0 = g_q[lane], q1 = g_q[32 + lane];
    float lmax = -3.4e38f;
    for (int n = lo + warp; n < hi; n += 4) {
        float v = g_h[(size_t)n * 64 + lane] * q0 + g_h[(size_t)n * 64 + 32 + lane] * q1;
#pragma unroll
        for (int off = 16; off; off >>= 1) v += __shfl_xor_sync(0xffffffffu, v, off);
        lmax = fmaxf(lmax, v);
    }
    if (lane == 0) s_max[warp] = lmax;
    __syncthreads();
    float emax = fmaxf(fmaxf(s_max[0], s_max[1]), fmaxf(s_max[2], s_max[3]));
    float p0 = 0.f, p1 = 0.f, ws = 0.f;
    for (int n = lo + warp; n < hi; n += 4) {
        float h0 = g_h[(size_t)n * 64 + lane], h1v = g_h[(size_t)n * 64 + 32 + lane];
        float v = h0 * q0 + h1v * q1;
#pragma unroll
        for (int off = 16; off; off >>= 1) v += __shfl_xor_sync(0xffffffffu, v, off);
        float c = expf(v - emax);
        p0 += c * h0; p1 += c * h1v; ws += c;
    }
    s_pool[warp][lane] = p0; s_pool[warp][32 + lane] = p1;
    if (lane == 0) s_ws[warp] = ws;
    __syncthreads();
    if (t < 64) {
        float ps = s_pool[0][t] + s_pool[1][t] + s_pool[2][t] + s_pool[3][t];
        float wtot = s_ws[0] + s_ws[1] + s_ws[2] + s_ws[3];
        s_r[t] = (wtot > 0.f) ? ps / wtot : 0.f;
    }
    __syncthreads();
    if (t < 2) {
        float acc = bias[t];
        for (int d = 0; d < 64; d++)
            acc += g_q[d] * W[d * 2 + t] + s_r[d] * W[(64 + d) * 2 + t];
        outp[b * 2 + t] = acc;
    }
}

// ---------------- launch ----------------
extern "C" void kernel_launch(void* const* d_in, const int* in_sizes, int n_in,
                              void* d_out, int out_size) {
    const float* x          = (const float*)d_in[0];
    const float* edge_attr  = (const float*)d_in[1];
    const int*   edge_index = (const int*)  d_in[2];
    const int*   batch      = (const int*)  d_in[3];
    const int*   stem_idx   = (const int*)  d_in[4];
    const int*   jbond_idx  = (const int*)  d_in[5];
    const float* lin0_w   = (const float*)d_in[6];
    const float* lin0_b   = (const float*)d_in[7];
    const float* net_w1   = (const float*)d_in[8];
    const float* net_b1   = (const float*)d_in[9];
    const float* net_w2   = (const float*)d_in[10];
    const float* net_b2   = (const float*)d_in[11];
    const float* conv_root= (const float*)d_in[12];
    const float* conv_bias= (const float*)d_in[13];
    const float* gru_w_ih = (const float*)d_in[14];
    const float* gru_w_hh = (const float*)d_in[15];
    const float* gru_b_ih = (const float*)d_in[16];
    const float* gru_b_hh = (const float*)d_in[17];
    const float* n2s_w1   = (const float*)d_in[18];
    const float* n2s_b1   = (const float*)d_in[19];
    const float* n2s_w2   = (const float*)d_in[20];
    const float* n2s_b2   = (const float*)d_in[21];
    const float* n2j_w1   = (const float*)d_in[22];
    const float* n2j_b1   = (const float*)d_in[23];
    const float* n2j_w2   = (const float*)d_in[24];
    const float* n2j_b2   = (const float*)d_in[25];
    const float* s2s_b_ih = (const float*)d_in[28];
    const float* s2s_b_hh = (const float*)d_in[29];
    const float* lin_out_w= (const float*)d_in[30];
    const float* lin_out_b= (const float*)d_in[31];
    float* out = (float*)d_out;

    const int* src = edge_index;             // edge_index[0]
    const int* dst = edge_index + N_EDGES;   // edge_index[1]

    zero_deg_kernel<<<N_NODES / 256, 256>>>();
    deg_kernel<<<(N_EDGES + 255) / 256, 256>>>(dst);
    invdeg_kernel<<<N_NODES / 256, 256>>>();
    zero_agg_kernel<<<N_NODES * DIM / 4 / 256, 256>>>();
    lin0_kernel<<<N_NODES * DIM / 256, 256>>>(x, lin0_w, lin0_b);
    h1_kernel<<<N_EDGES * DIM / 256, 256>>>(edge_attr, net_w1, net_b1);
    w2y_kernel<<<(Y_COLS * 64 + 255) / 256, 256>>>(net_w2, net_b2);
    prep_weights_kernel<<<112, 256>>>(conv_root, gru_w_ih, gru_w_hh);

    for (int it = 0; it < 6; it++) {
        y_gemm_tc<<<dim3(Y_COLS / 128, N_NODES / 128), 256>>>();
        msg_y_kernel<<<N_EDGES / 16, 256>>>(src, dst);
        node_update_tc<<<N_NODES / 64, 256>>>(conv_bias, gru_b_ih, gru_b_hh);
    }

    stem_kernel<<<N_STEMS, 128>>>(stem_idx, n2s_w1, n2s_b1, n2s_w2, n2s_b2, out);
    jbond_kernel<<<N_JBONDS, 128>>>(jbond_idx, n2j_w1, n2j_b1, n2j_w2, n2j_b2, out);
    s2s_q_kernel<<<1, 64>>>(s2s_b_ih, s2s_b_hh);
    pool_kernel<<<N_GRAPHS, 128>>>(batch, lin_out_w, lin_out_b, out);
}

// round 8
// speedup vs baseline: 1.2075x; 1.2075x over previous
#include <cuda_runtime.h>
#include <cuda_bf16.h>
#include <cstdint>
#include <math.h>

#define N_NODES   8192
#define N_EDGES   16384
#define N_GRAPHS  256
#define N_STEMS   2048
#define N_JBONDS  1024
#define DIM       64
#define NUM_FEAT  14
#define NUM_OUT   105

// ---------------- scratch (device globals; no allocations allowed) ----------------
__device__ __nv_bfloat16 g_w2r[65 * 64 * 64];   // W2 rearranged [chunk k][o][i] bf16; chunk 64 = B2
__device__ float g_h1f[N_EDGES * DIM];          // edge-net hidden (fp32)
__device__ float g_rt[64 * 64];                 // conv_root^T [o][i] fp32
__device__ float g_wihT[192 * 64];              // gru_w_ih^T [o][i] fp32
__device__ float g_whhT[192 * 64];              // gru_w_hh^T [o][i] fp32
__device__ float g_h[N_NODES * DIM];            // node state
__device__ float g_agg[N_NODES * DIM];          // scatter accumulator
__device__ float g_deg[N_NODES];                // becomes 1/max(deg,1)
__device__ float g_q[DIM];

__device__ __forceinline__ float lrelu(float v) { return v > 0.f ? v : 0.01f * v; }
__device__ __forceinline__ float sigm(float v)  { return 1.f / (1.f + expf(-v)); }

__device__ __forceinline__ void mma_bf16(float* c, const uint32_t* a, const uint32_t* b) {
    asm volatile(
        "mma.sync.aligned.m16n8k16.row.col.f32.bf16.bf16.f32 "
        "{%0,%1,%2,%3}, {%4,%5,%6,%7}, {%8,%9}, {%0,%1,%2,%3};"
        : "+f"(c[0]), "+f"(c[1]), "+f"(c[2]), "+f"(c[3])
        : "r"(a[0]), "r"(a[1]), "r"(a[2]), "r"(a[3]), "r"(b[0]), "r"(b[1]));
}

__device__ __forceinline__ uint32_t hmul2b(uint32_t a, uint32_t s) {
    uint32_t r;
    asm("mul.bf16x2 %0, %1, %2;" : "=r"(r) : "r"(a), "r"(s));
    return r;
}

__device__ __forceinline__ uint32_t f2tf32(float f) {
    uint32_t r;
    asm("cvt.rna.tf32.f32 %0, %1;" : "=r"(r) : "f"(f));
    return r;
}

__device__ __forceinline__ void mma_tf32(float* c, const uint32_t* a, const uint32_t* b) {
    asm volatile(
        "mma.sync.aligned.m16n8k8.row.col.f32.tf32.tf32.f32 "
        "{%0,%1,%2,%3}, {%4,%5,%6,%7}, {%8,%9}, {%0,%1,%2,%3};"
        : "+f"(c[0]), "+f"(c[1]), "+f"(c[2]), "+f"(c[3])
        : "r"(a[0]), "r"(a[1]), "r"(a[2]), "r"(a[3]), "r"(b[0]), "r"(b[1]));
}

// ---------------- degree / init ----------------
__global__ void zero_deg_kernel() {
    g_deg[blockIdx.x * 256 + threadIdx.x] = 0.f;
}
__global__ void deg_kernel(const int* __restrict__ dst) {
    int e = blockIdx.x * 256 + threadIdx.x;
    if (e < N_EDGES) atomicAdd(&g_deg[dst[e]], 1.0f);
}
__global__ void invdeg_kernel() {
    int i = blockIdx.x * 256 + threadIdx.x;
    g_deg[i] = 1.0f / fmaxf(g_deg[i], 1.0f);
}
__global__ void zero_agg_kernel() {
    int i = blockIdx.x * 256 + threadIdx.x;
    ((float4*)g_agg)[i] = make_float4(0.f, 0.f, 0.f, 0.f);
}

// ---------------- lin0: h = lrelu(x @ W + b) ----------------
__global__ void lin0_kernel(const float* __restrict__ x,
                            const float* __restrict__ W,
                            const float* __restrict__ b) {
    int tid = blockIdx.x * 256 + threadIdx.x;
    int n = tid >> 6, o = tid & 63;
    float acc = b[o];
#pragma unroll
    for (int i = 0; i < NUM_FEAT; i++) acc += x[n * NUM_FEAT + i] * W[i * DIM + o];
    g_h[(size_t)n * DIM + o] = lrelu(acc);
}

// ---------------- edge net hidden: h1 = lrelu(ea @ W1 + b1), fp32 ----------------
__global__ void h1_kernel(const float* __restrict__ ea,
                          const float* __restrict__ W1,
                          const float* __restrict__ b1) {
    int tid = blockIdx.x * 256 + threadIdx.x;
    int e = tid >> 6, k = tid & 63;
    float acc = b1[k];
#pragma unroll
    for (int i = 0; i < 4; i++) acc += ea[e * 4 + i] * W1[i * DIM + k];
    g_h1f[(size_t)e * DIM + k] = lrelu(acc);
}

// ---------------- W2 rearrange: g_w2r[k][o][i] = W2[k][i*64+o]; chunk 64 = B2 ------
__global__ void w2r_kernel(const float* __restrict__ W2, const float* __restrict__ b2) {
    int idx = blockIdx.x * 256 + threadIdx.x;
    if (idx >= 65 * 4096) return;
    int c = idx >> 12, r = idx & 4095;
    int o = r >> 6, i = r & 63;
    float v = (c < 64) ? W2[(c << 12) + (i << 6) + o] : b2[(i << 6) + o];
    g_w2r[idx] = __float2bfloat16(v);
}

// ---------------- GRU/root weights -> transposed fp32 ----------------
__global__ void prep_weights_kernel(const float* __restrict__ R,
                                    const float* __restrict__ Wih,
                                    const float* __restrict__ Whh) {
    int i = blockIdx.x * 256 + threadIdx.x;     // 0 .. 28671
    if (i < 4096) {
        int o = i >> 6, k = i & 63;
        g_rt[o * 64 + k] = R[k * 64 + o];
    } else if (i < 4096 + 12288) {
        int j = i - 4096;
        int o = j >> 6, k = j & 63;
        g_wihT[o * 64 + k] = Wih[k * 192 + o];
    } else {
        int j = i - 4096 - 12288;
        int o = j >> 6, k = j & 63;
        g_whhT[o * 64 + k] = Whh[k * 192 + o];
    }
}

// ================= fused factorized message GEMM ==================================
// msg_e = sum_k h1_ek * (v_e @ W2_k) + v_e @ B2,  v_e = h[src(e)], scatter to agg[dst].
// Block: 64 edges, 256 threads (warps 2m x 4n), 2 CTAs/SM. A-side bf16 h1 scaling;
// mma accumulates directly into c over all 65 chunks. W2 cp.async double-buffered.
//
// dynamic smem layout (bytes):
//   [0, 73728)         w2sm: 2 bufs x [4 chunks][64 o][72 i] bf16
//   [73728, 82944)     vsm:  [64][72] bf16
//   [82944, 100352)    h1b:  [64][68] uint32 (bf16x2 duplicated)
//   [100352, 100608)   dssm: [64] int
//   [100608, 100864)   ssm:  [64] int
#define MSG_SMEM_W2   0
#define MSG_SMEM_V    73728
#define MSG_SMEM_H1   82944
#define MSG_SMEM_DS   100352
#define MSG_SMEM_SS   100608
#define MSG_SMEM_TOTAL 100864
#define W2BUF_BYTES   36864

__device__ __forceinline__ void prefetch_w2(int base_chunk, int nch, int buf,
                                            int tid, uint32_t smem_base) {
    int tasks = nch * 512;                      // nch * 64 rows * 8 segs
    for (int idx = tid; idx < tasks; idx += 256) {
        int cc = idx >> 9;
        int o  = (idx >> 3) & 63;
        int s  = idx & 7;
        const __nv_bfloat16* gp = &g_w2r[((size_t)(base_chunk + cc) * 64 + o) * 64 + s * 8];
        uint32_t sp = smem_base + MSG_SMEM_W2 + buf * W2BUF_BYTES
                      + ((cc * 64 + o) * 72 + s * 8) * 2;
        asm volatile("cp.async.cg.shared.global [%0], [%1], 16;" :: "r"(sp), "l"(gp));
    }
    asm volatile("cp.async.commit_group;" ::: "memory");
}

__global__ __launch_bounds__(256, 2) void msg_gemm(const int* __restrict__ src,
                                                   const int* __restrict__ dst) {
    extern __shared__ char smem[];
    __nv_bfloat16* vsm = (__nv_bfloat16*)(smem + MSG_SMEM_V);
    uint32_t* h1b = (uint32_t*)(smem + MSG_SMEM_H1);
    int* dssm = (int*)(smem + MSG_SMEM_DS);
    int* ssm  = (int*)(smem + MSG_SMEM_SS);
    uint32_t smem_base = (uint32_t)__cvta_generic_to_shared(smem);

    int tid = threadIdx.x;
    int e0 = blockIdx.x * 64;

    if (tid < 64) {
        ssm[tid] = src[e0 + tid];
        dssm[tid] = dst[e0 + tid];
    }
    // kick off W2 group 0 (chunks 0..3) into buf 0
    prefetch_w2(0, 4, 0, tid, smem_base);
    __syncthreads();                            // ssm visible

    // gather v (bf16) and h1 (bf16x2-dup)
#pragma unroll
    for (int p = 0; p < 4; p++) {
        int idx = tid + p * 256;                // 1024 tasks: 64 rows x 16 segs
        int row = idx >> 4, seg = idx & 15;
        int s = ssm[row];
        float4 v = *(const float4*)&g_h[(size_t)s * 64 + seg * 4];
        __nv_bfloat162 p0 = __floats2bfloat162_rn(v.x, v.y);
        __nv_bfloat162 p1 = __floats2bfloat162_rn(v.z, v.w);
        uint2 u; u.x = *(uint32_t*)&p0; u.y = *(uint32_t*)&p1;
        *(uint2*)&vsm[row * 72 + seg * 4] = u;
    }
#pragma unroll
    for (int p = 0; p < 4; p++) {
        int idx = tid + p * 256;                // 1024 tasks: 64 rows x 16 quads
        int row = idx >> 4, k4 = (idx & 15) * 4;
        float4 hv = *(const float4*)&g_h1f[(size_t)(e0 + row) * 64 + k4];
        __nv_bfloat16 b0 = __float2bfloat16(hv.x);
        __nv_bfloat16 b1 = __float2bfloat16(hv.y);
        __nv_bfloat16 b2 = __float2bfloat16(hv.z);
        __nv_bfloat16 b3 = __float2bfloat16(hv.w);
        uint32_t d0 = ((uint32_t)*(uint16_t*)&b0) * 0x00010001u;
        uint32_t d1 = ((uint32_t)*(uint16_t*)&b1) * 0x00010001u;
        uint32_t d2 = ((uint32_t)*(uint16_t*)&b2) * 0x00010001u;
        uint32_t d3 = ((uint32_t)*(uint16_t*)&b3) * 0x00010001u;
        uint4 q; q.x = d0; q.y = d1; q.z = d2; q.w = d3;
        *(uint4*)&h1b[row * 68 + k4] = q;
    }
    __syncthreads();

    int w = tid >> 5, lane = tid & 31;
    int warpM = w >> 2, warpN = w & 3;          // 2 m-warps x 4 n-warps
    int rowbase = warpM * 32;
    int g = lane >> 2, t4 = lane & 3;

    // v fragments (persist in registers for all chunks)
    uint32_t vfrag[2][4][4];
#pragma unroll
    for (int mt = 0; mt < 2; mt++)
#pragma unroll
        for (int ks = 0; ks < 4; ks++) {
            int r0 = rowbase + mt * 16 + g;
            int cl = ks * 16 + 2 * t4;
            vfrag[mt][ks][0] = *(const uint32_t*)&vsm[r0 * 72 + cl];
            vfrag[mt][ks][1] = *(const uint32_t*)&vsm[(r0 + 8) * 72 + cl];
            vfrag[mt][ks][2] = *(const uint32_t*)&vsm[r0 * 72 + cl + 8];
            vfrag[mt][ks][3] = *(const uint32_t*)&vsm[(r0 + 8) * 72 + cl + 8];
        }

    float c[2][2][4];
#pragma unroll
    for (int mt = 0; mt < 2; mt++)
#pragma unroll
        for (int ni = 0; ni < 2; ni++)
#pragma unroll
            for (int r = 0; r < 4; r++) c[mt][ni][r] = 0.f;

#pragma unroll 1
    for (int grp = 0; grp < 16; grp++) {
        asm volatile("cp.async.wait_group 0;" ::: "memory");
        __syncthreads();
        int buf = grp & 1;
        if (grp < 15) prefetch_w2((grp + 1) * 4, 4, (grp + 1) & 1, tid, smem_base);
        else          prefetch_w2(64, 1, 0, tid, smem_base);
        const __nv_bfloat16* w2p =
            (const __nv_bfloat16*)(smem + MSG_SMEM_W2 + buf * W2BUF_BYTES);
#pragma unroll 1
        for (int cc = 0; cc < 4; cc++) {
            int k = grp * 4 + cc;
            uint32_t hA[2], hB[2];
#pragma unroll
            for (int mt = 0; mt < 2; mt++) {
                int rA = rowbase + mt * 16 + g;
                hA[mt] = h1b[rA * 68 + k];
                hB[mt] = h1b[(rA + 8) * 68 + k];
            }
#pragma unroll
            for (int ks = 0; ks < 4; ks++) {
                uint32_t b[2][2];
#pragma unroll
                for (int ni = 0; ni < 2; ni++) {
                    int orow = warpN * 16 + ni * 8 + g;
                    int ib = ks * 16 + 2 * t4;
                    b[ni][0] = *(const uint32_t*)&w2p[(cc * 64 + orow) * 72 + ib];
                    b[ni][1] = *(const uint32_t*)&w2p[(cc * 64 + orow) * 72 + ib + 8];
                }
#pragma unroll
                for (int mt = 0; mt < 2; mt++) {
                    uint32_t sa[4];
                    sa[0] = hmul2b(vfrag[mt][ks][0], hA[mt]);
                    sa[1] = hmul2b(vfrag[mt][ks][1], hB[mt]);
                    sa[2] = hmul2b(vfrag[mt][ks][2], hA[mt]);
                    sa[3] = hmul2b(vfrag[mt][ks][3], hB[mt]);
#pragma unroll
                    for (int ni = 0; ni < 2; ni++)
                        mma_bf16(c[mt][ni], sa, b[ni]);
                }
            }
        }
        __syncthreads();
    }

    // B2 chunk (unit coefficient) — accumulate directly with unscaled vfrag
    asm volatile("cp.async.wait_group 0;" ::: "memory");
    __syncthreads();
    {
        const __nv_bfloat16* w2p = (const __nv_bfloat16*)(smem + MSG_SMEM_W2);  // buf 0
#pragma unroll
        for (int ks = 0; ks < 4; ks++) {
            uint32_t b[2][2];
#pragma unroll
            for (int ni = 0; ni < 2; ni++) {
                int orow = warpN * 16 + ni * 8 + g;
                int ib = ks * 16 + 2 * t4;
                b[ni][0] = *(const uint32_t*)&w2p[orow * 72 + ib];
                b[ni][1] = *(const uint32_t*)&w2p[orow * 72 + ib + 8];
            }
#pragma unroll
            for (int mt = 0; mt < 2; mt++)
#pragma unroll
                for (int ni = 0; ni < 2; ni++)
                    mma_bf16(c[mt][ni], vfrag[mt][ks], b[ni]);
        }
    }

    // scatter into agg
#pragma unroll
    for (int mt = 0; mt < 2; mt++)
#pragma unroll
        for (int half = 0; half < 2; half++) {
            int row = rowbase + mt * 16 + g + half * 8;
            int d = dssm[row];
            float* ap = &g_agg[(size_t)d * 64 + warpN * 16];
#pragma unroll
            for (int ni = 0; ni < 2; ni++) {
                atomicAdd(&ap[ni * 8 + 2 * t4],     c[mt][ni][half * 2 + 0]);
                atomicAdd(&ap[ni * 8 + 2 * t4 + 1], c[mt][ni][half * 2 + 1]);
            }
        }
}

// ---------------- tf32 tensor-core NNConv epilogue + GRU (64 nodes/block) ----------
__global__ __launch_bounds__(256) void node_update_tc(
    const float* __restrict__ cbias,
    const float* __restrict__ bih, const float* __restrict__ bhh) {
    __shared__ float hsm[64][68];
    __shared__ float msm[64][68];
    int n0 = blockIdx.x * 64;
    int tid = threadIdx.x;

#pragma unroll
    for (int i = 0; i < 4; i++) {
        int idx = tid + i * 256;
        int row = idx >> 4, c4 = (idx & 15) * 4;
        *(float4*)&hsm[row][c4] = *(const float4*)&g_h[(size_t)(n0 + row) * 64 + c4];
    }
    __syncthreads();

    int w = tid >> 5, lane = tid & 31;
    int g = lane >> 2, t4 = lane & 3;
    int c0 = w * 8 + 2 * t4;

    float accB[4][4] = {};
#pragma unroll
    for (int ks = 0; ks < 8; ks++) {
        int k0 = ks * 8;
        uint32_t rb[2];
        int nrow = w * 8 + g;
        rb[0] = f2tf32(g_rt[nrow * 64 + k0 + t4]);
        rb[1] = f2tf32(g_rt[nrow * 64 + k0 + t4 + 4]);
#pragma unroll
        for (int mt = 0; mt < 4; mt++) {
            int r0 = mt * 16 + g;
            uint32_t a[4];
            a[0] = f2tf32(hsm[r0][k0 + t4]);
            a[1] = f2tf32(hsm[r0 + 8][k0 + t4]);
            a[2] = f2tf32(hsm[r0][k0 + t4 + 4]);
            a[3] = f2tf32(hsm[r0 + 8][k0 + t4 + 4]);
            mma_tf32(accB[mt], a, rb);
        }
    }
    {
        float2 cb = *(const float2*)&cbias[c0];
#pragma unroll
        for (int mt = 0; mt < 4; mt++) {
#pragma unroll
            for (int half = 0; half < 2; half++) {
                int row = mt * 16 + g + half * 8;
                int node = n0 + row;
                float inv = g_deg[node];
                float2 ag = *(float2*)&g_agg[(size_t)node * 64 + c0];
                *(float2*)&g_agg[(size_t)node * 64 + c0] = make_float2(0.f, 0.f);
                msm[row][c0]     = lrelu(ag.x * inv + accB[mt][half * 2 + 0] + cb.x);
                msm[row][c0 + 1] = lrelu(ag.y * inv + accB[mt][half * 2 + 1] + cb.y);
            }
        }
    }
    __syncthreads();

    float accI[4][3][4] = {};
    float accH[4][3][4] = {};
#pragma unroll
    for (int ks = 0; ks < 8; ks++) {
        int k0 = ks * 8;
        uint32_t bi[3][2], bh[3][2];
#pragma unroll
        for (int j = 0; j < 3; j++) {
            int nrow = j * 64 + w * 8 + g;
            bi[j][0] = f2tf32(g_wihT[nrow * 64 + k0 + t4]);
            bi[j][1] = f2tf32(g_wihT[nrow * 64 + k0 + t4 + 4]);
            bh[j][0] = f2tf32(g_whhT[nrow * 64 + k0 + t4]);
            bh[j][1] = f2tf32(g_whhT[nrow * 64 + k0 + t4 + 4]);
        }
#pragma unroll
        for (int mt = 0; mt < 4; mt++) {
            int r0 = mt * 16 + g;
            uint32_t am[4], ah[4];
            am[0] = f2tf32(msm[r0][k0 + t4]);
            am[1] = f2tf32(msm[r0 + 8][k0 + t4]);
            am[2] = f2tf32(msm[r0][k0 + t4 + 4]);
            am[3] = f2tf32(msm[r0 + 8][k0 + t4 + 4]);
            ah[0] = f2tf32(hsm[r0][k0 + t4]);
            ah[1] = f2tf32(hsm[r0 + 8][k0 + t4]);
            ah[2] = f2tf32(hsm[r0][k0 + t4 + 4]);
            ah[3] = f2tf32(hsm[r0 + 8][k0 + t4 + 4]);
#pragma unroll
            for (int j = 0; j < 3; j++) {
                mma_tf32(accI[mt][j], am, bi[j]);
                mma_tf32(accH[mt][j], ah, bh[j]);
            }
        }
    }

    float2 b_ir = *(const float2*)&bih[c0];
    float2 b_iz = *(const float2*)&bih[64 + c0];
    float2 b_in = *(const float2*)&bih[128 + c0];
    float2 b_hr = *(const float2*)&bhh[c0];
    float2 b_hz = *(const float2*)&bhh[64 + c0];
    float2 b_hn = *(const float2*)&bhh[128 + c0];
#pragma unroll
    for (int mt = 0; mt < 4; mt++) {
#pragma unroll
        for (int half = 0; half < 2; half++) {
            int row = mt * 16 + g + half * 8;
            int node = n0 + row;
            int o = half * 2;
            float2 hold = make_float2(hsm[row][c0], hsm[row][c0 + 1]);
            float rx = sigm(accI[mt][0][o] + b_ir.x + accH[mt][0][o] + b_hr.x);
            float zx = sigm(accI[mt][1][o] + b_iz.x + accH[mt][1][o] + b_hz.x);
            float nx = tanhf(accI[mt][2][o] + b_in.x + rx * (accH[mt][2][o] + b_hn.x));
            float ry = sigm(accI[mt][0][o + 1] + b_ir.y + accH[mt][0][o + 1] + b_hr.y);
            float zy = sigm(accI[mt][1][o + 1] + b_iz.y + accH[mt][1][o + 1] + b_hz.y);
            float ny = tanhf(accI[mt][2][o + 1] + b_in.y + ry * (accH[mt][2][o + 1] + b_hn.y));
            float2 hn;
            hn.x = (1.f - zx) * nx + zx * hold.x;
            hn.y = (1.f - zy) * ny + zy * hold.y;
            *(float2*)&g_h[(size_t)node * 64 + c0] = hn;
        }
    }
}

// ---------------- stem head ----------------
__global__ __launch_bounds__(128) void stem_kernel(const int* __restrict__ idx,
                                                   const float* __restrict__ W1, const float* __restrict__ b1,
                                                   const float* __restrict__ W2, const float* __restrict__ b2,
                                                   float* __restrict__ outp) {
    __shared__ float row[64], hid[64];
    int s = blockIdx.x, t = threadIdx.x;
    int atom = idx[s];
    if (t < 64) row[t] = g_h[(size_t)atom * 64 + t];
    __syncthreads();
    if (t < 64) {
        float acc = b1[t];
#pragma unroll
        for (int i = 0; i < 64; i++) acc += row[i] * W1[i * 64 + t];
        hid[t] = lrelu(acc);
    }
    __syncthreads();
    for (int o = t; o < NUM_OUT; o += 128) {
        float acc = b2[o];
#pragma unroll
        for (int i = 0; i < 64; i++) acc += hid[i] * W2[i * NUM_OUT + o];
        outp[512 + (size_t)s * NUM_OUT + o] = acc;
    }
}

// ---------------- jbond head ----------------
__global__ __launch_bounds__(128) void jbond_kernel(const int* __restrict__ idx,
                                                    const float* __restrict__ W1, const float* __restrict__ b1,
                                                    const float* __restrict__ w2, const float* __restrict__ b2,
                                                    float* __restrict__ outp) {
    __shared__ float row[2][64];
    __shared__ float warpsum[4];
    int jb = blockIdx.x, t = threadIdx.x;
    int a = t >> 6, tt = t & 63;
    int atom = idx[jb * 2 + a];
    row[a][tt] = g_h[(size_t)atom * 64 + tt];
    __syncthreads();
    float acc = b1[tt];
#pragma unroll
    for (int i = 0; i < 64; i++) acc += row[a][i] * W1[i * 64 + tt];
    float p = lrelu(acc) * w2[tt];
#pragma unroll
    for (int off = 16; off; off >>= 1) p += __shfl_xor_sync(0xffffffffu, p, off);
    if ((t & 31) == 0) warpsum[t >> 5] = p;
    __syncthreads();
    if (t == 0) {
        float p0 = warpsum[0] + warpsum[1] + b2[0];
        float p1 = warpsum[2] + warpsum[3] + b2[0];
        outp[512 + (size_t)N_STEMS * NUM_OUT + jb] = 0.5f * (p0 + p1);
    }
}

// ---------------- Set2Set q (bias-only; identical for all graphs) ----------------
__global__ void s2s_q_kernel(const float* __restrict__ bih, const float* __restrict__ bhh) {
    int d = threadIdx.x;
    float bi = bih[d]       + bhh[d];
    float bg = bih[128 + d] + bhh[128 + d];
    float bo = bih[192 + d] + bhh[192 + d];
    float c = sigm(bi) * tanhf(bg);
    g_q[d] = sigm(bo) * tanhf(c);
}

// ---------------- per-graph attention pool + lin_out ----------------
__global__ __launch_bounds__(128) void pool_kernel(const int* __restrict__ batch,
                                                   const float* __restrict__ W, const float* __restrict__ bias,
                                                   float* __restrict__ outp) {
    __shared__ int s_lo, s_hi;
    __shared__ float s_max[4], s_ws[4], s_pool[4][64], s_r[64];
    int b = blockIdx.x, t = threadIdx.x;
    if (t == 0) {
        int lo = 0, hi = N_NODES;
        while (lo < hi) { int m = (lo + hi) >> 1; if (batch[m] < b) lo = m + 1; else hi = m; }
        s_lo = lo;
        int lo2 = lo, hi2 = N_NODES;
        while (lo2 < hi2) { int m = (lo2 + hi2) >> 1; if (batch[m] < b + 1) lo2 = m + 1; else hi2 = m; }
        s_hi = lo2;
    }
    __syncthreads();
    int lo = s_lo, hi = s_hi;
    int warp = t >> 5, lane = t & 31;
    float q0 = g_q[lane], q1 = g_q[32 + lane];
    float lmax = -3.4e38f;
    for (int n = lo + warp; n < hi; n += 4) {
        float v = g_h[(size_t)n * 64 + lane] * q0 + g_h[(size_t)n * 64 + 32 + lane] * q1;
#pragma unroll
        for (int off = 16; off; off >>= 1) v += __shfl_xor_sync(0xffffffffu, v, off);
        lmax = fmaxf(lmax, v);
    }
    if (lane == 0) s_max[warp] = lmax;
    __syncthreads();
    float emax = fmaxf(fmaxf(s_max[0], s_max[1]), fmaxf(s_max[2], s_max[3]));
    float p0 = 0.f, p1 = 0.f, ws = 0.f;
    for (int n = lo + warp; n < hi; n += 4) {
        float h0 = g_h[(size_t)n * 64 + lane], h1v = g_h[(size_t)n * 64 + 32 + lane];
        float v = h0 * q0 + h1v * q1;
#pragma unroll
        for (int off = 16; off; off >>= 1) v += __shfl_xor_sync(0xffffffffu, v, off);
        float c = expf(v - emax);
        p0 += c * h0; p1 += c * h1v; ws += c;
    }
    s_pool[warp][lane] = p0; s_pool[warp][32 + lane] = p1;
    if (lane == 0) s_ws[warp] = ws;
    __syncthreads();
    if (t < 64) {
        float ps = s_pool[0][t] + s_pool[1][t] + s_pool[2][t] + s_pool[3][t];
        float wtot = s_ws[0] + s_ws[1] + s_ws[2] + s_ws[3];
        s_r[t] = (wtot > 0.f) ? ps / wtot : 0.f;
    }
    __syncthreads();
    if (t < 2) {
        float acc = bias[t];
        for (int d = 0; d < 64; d++)
            acc += g_q[d] * W[d * 2 + t] + s_r[d] * W[(64 + d) * 2 + t];
        outp[b * 2 + t] = acc;
    }
}

// ---------------- launch ----------------
extern "C" void kernel_launch(void* const* d_in, const int* in_sizes, int n_in,
                              void* d_out, int out_size) {
    const float* x          = (const float*)d_in[0];
    const float* edge_attr  = (const float*)d_in[1];
    const int*   edge_index = (const int*)  d_in[2];
    const int*   batch      = (const int*)  d_in[3];
    const int*   stem_idx   = (const int*)  d_in[4];
    const int*   jbond_idx  = (const int*)  d_in[5];
    const float* lin0_w   = (const float*)d_in[6];
    const float* lin0_b   = (const float*)d_in[7];
    const float* net_w1   = (const float*)d_in[8];
    const float* net_b1   = (const float*)d_in[9];
    const float* net_w2   = (const float*)d_in[10];
    const float* net_b2   = (const float*)d_in[11];
    const float* conv_root= (const float*)d_in[12];
    const float* conv_bias= (const float*)d_in[13];
    const float* gru_w_ih = (const float*)d_in[14];
    const float* gru_w_hh = (const float*)d_in[15];
    const float* gru_b_ih = (const float*)d_in[16];
    const float* gru_b_hh = (const float*)d_in[17];
    const float* n2s_w1   = (const float*)d_in[18];
    const float* n2s_b1   = (const float*)d_in[19];
    const float* n2s_w2   = (const float*)d_in[20];
    const float* n2s_b2   = (const float*)d_in[21];
    const float* n2j_w1   = (const float*)d_in[22];
    const float* n2j_b1   = (const float*)d_in[23];
    const float* n2j_w2   = (const float*)d_in[24];
    const float* n2j_b2   = (const float*)d_in[25];
    const float* s2s_b_ih = (const float*)d_in[28];
    const float* s2s_b_hh = (const float*)d_in[29];
    const float* lin_out_w= (const float*)d_in[30];
    const float* lin_out_b= (const float*)d_in[31];
    float* out = (float*)d_out;

    const int* src = edge_index;             // edge_index[0]
    const int* dst = edge_index + N_EDGES;   // edge_index[1]

    cudaFuncSetAttribute(msg_gemm, cudaFuncAttributeMaxDynamicSharedMemorySize,
                         MSG_SMEM_TOTAL);

    zero_deg_kernel<<<N_NODES / 256, 256>>>();
    deg_kernel<<<(N_EDGES + 255) / 256, 256>>>(dst);
    invdeg_kernel<<<N_NODES / 256, 256>>>();
    zero_agg_kernel<<<N_NODES * DIM / 4 / 256, 256>>>();
    lin0_kernel<<<N_NODES * DIM / 256, 256>>>(x, lin0_w, lin0_b);
    h1_kernel<<<N_EDGES * DIM / 256, 256>>>(edge_attr, net_w1, net_b1);
    w2r_kernel<<<(65 * 4096 + 255) / 256, 256>>>(net_w2, net_b2);
    prep_weights_kernel<<<112, 256>>>(conv_root, gru_w_ih, gru_w_hh);

    for (int it = 0; it < 6; it++) {
        msg_gemm<<<N_EDGES / 64, 256, MSG_SMEM_TOTAL>>>(src, dst);
        node_update_tc<<<N_NODES / 64, 256>>>(conv_bias, gru_b_ih, gru_b_hh);
    }

    stem_kernel<<<N_STEMS, 128>>>(stem_idx, n2s_w1, n2s_b1, n2s_w2, n2s_b2, out);
    jbond_kernel<<<N_JBONDS, 128>>>(jbond_idx, n2j_w1, n2j_b1, n2j_w2, n2j_b2, out);
    s2s_q_kernel<<<1, 64>>>(s2s_b_ih, s2s_b_hh);
    pool_kernel<<<N_GRAPHS, 128>>>(batch, lin_out_w, lin_out_b, out);
}

// round 9
// speedup vs baseline: 1.3452x; 1.1140x over previous
#include <cuda_runtime.h>
#include <cuda_bf16.h>
#include <cstdint>
#include <math.h>

#define N_NODES   8192
#define N_EDGES   16384
#define N_GRAPHS  256
#define N_STEMS   2048
#define N_JBONDS  1024
#define DIM       64
#define NUM_FEAT  14
#define NUM_OUT   105

// ---------------- scratch (device globals; no allocations allowed) ----------------
__device__ __nv_bfloat16 g_w2r[65 * 64 * 64];   // W2 rearranged [chunk k][o][i] bf16; chunk 64 = B2
__device__ float g_h1f[N_EDGES * DIM];          // edge-net hidden (fp32)
__device__ float g_rt[64 * 64];                 // conv_root^T [o][i] fp32
__device__ float g_wihT[192 * 64];              // gru_w_ih^T [o][i] fp32
__device__ float g_whhT[192 * 64];              // gru_w_hh^T [o][i] fp32
__device__ float g_h[N_NODES * DIM];            // node state
__device__ float g_agg[N_NODES * DIM];          // scatter accumulator
__device__ float g_deg[N_NODES];                // becomes 1/max(deg,1)
__device__ float g_q[DIM];

__device__ __forceinline__ float lrelu(float v) { return v > 0.f ? v : 0.01f * v; }
__device__ __forceinline__ float sigm(float v)  { return 1.f / (1.f + expf(-v)); }

__device__ __forceinline__ void mma_bf16(float* c, const uint32_t* a, const uint32_t* b) {
    asm volatile(
        "mma.sync.aligned.m16n8k16.row.col.f32.bf16.bf16.f32 "
        "{%0,%1,%2,%3}, {%4,%5,%6,%7}, {%8,%9}, {%0,%1,%2,%3};"
        : "+f"(c[0]), "+f"(c[1]), "+f"(c[2]), "+f"(c[3])
        : "r"(a[0]), "r"(a[1]), "r"(a[2]), "r"(a[3]), "r"(b[0]), "r"(b[1]));
}

__device__ __forceinline__ uint32_t hmul2b(uint32_t a, uint32_t s) {
    uint32_t r;
    asm("mul.bf16x2 %0, %1, %2;" : "=r"(r) : "r"(a), "r"(s));
    return r;
}

__device__ __forceinline__ uint32_t f2tf32(float f) {
    uint32_t r;
    asm("cvt.rna.tf32.f32 %0, %1;" : "=r"(r) : "f"(f));
    return r;
}

__device__ __forceinline__ void mma_tf32(float* c, const uint32_t* a, const uint32_t* b) {
    asm volatile(
        "mma.sync.aligned.m16n8k8.row.col.f32.tf32.tf32.f32 "
        "{%0,%1,%2,%3}, {%4,%5,%6,%7}, {%8,%9}, {%0,%1,%2,%3};"
        : "+f"(c[0]), "+f"(c[1]), "+f"(c[2]), "+f"(c[3])
        : "r"(a[0]), "r"(a[1]), "r"(a[2]), "r"(a[3]), "r"(b[0]), "r"(b[1]));
}

// ---------------- degree / init ----------------
__global__ void zero_deg_kernel() {
    g_deg[blockIdx.x * 256 + threadIdx.x] = 0.f;
}
__global__ void deg_kernel(const int* __restrict__ dst) {
    int e = blockIdx.x * 256 + threadIdx.x;
    if (e < N_EDGES) atomicAdd(&g_deg[dst[e]], 1.0f);
}
__global__ void invdeg_kernel() {
    int i = blockIdx.x * 256 + threadIdx.x;
    g_deg[i] = 1.0f / fmaxf(g_deg[i], 1.0f);
}
__global__ void zero_agg_kernel() {
    int i = blockIdx.x * 256 + threadIdx.x;
    ((float4*)g_agg)[i] = make_float4(0.f, 0.f, 0.f, 0.f);
}

// ---------------- lin0: h = lrelu(x @ W + b) ----------------
__global__ void lin0_kernel(const float* __restrict__ x,
                            const float* __restrict__ W,
                            const float* __restrict__ b) {
    int tid = blockIdx.x * 256 + threadIdx.x;
    int n = tid >> 6, o = tid & 63;
    float acc = b[o];
#pragma unroll
    for (int i = 0; i < NUM_FEAT; i++) acc += x[n * NUM_FEAT + i] * W[i * DIM + o];
    g_h[(size_t)n * DIM + o] = lrelu(acc);
}

// ---------------- edge net hidden: h1 = lrelu(ea @ W1 + b1), fp32 ----------------
__global__ void h1_kernel(const float* __restrict__ ea,
                          const float* __restrict__ W1,
                          const float* __restrict__ b1) {
    int tid = blockIdx.x * 256 + threadIdx.x;
    int e = tid >> 6, k = tid & 63;
    float acc = b1[k];
#pragma unroll
    for (int i = 0; i < 4; i++) acc += ea[e * 4 + i] * W1[i * DIM + k];
    g_h1f[(size_t)e * DIM + k] = lrelu(acc);
}

// ---------------- W2 rearrange: g_w2r[k][o][i] = W2[k][i*64+o]; chunk 64 = B2 ------
__global__ void w2r_kernel(const float* __restrict__ W2, const float* __restrict__ b2) {
    int idx = blockIdx.x * 256 + threadIdx.x;
    if (idx >= 65 * 4096) return;
    int c = idx >> 12, r = idx & 4095;
    int o = r >> 6, i = r & 63;
    float v = (c < 64) ? W2[(c << 12) + (i << 6) + o] : b2[(i << 6) + o];
    g_w2r[idx] = __float2bfloat16(v);
}

// ---------------- GRU/root weights -> transposed fp32 ----------------
__global__ void prep_weights_kernel(const float* __restrict__ R,
                                    const float* __restrict__ Wih,
                                    const float* __restrict__ Whh) {
    int i = blockIdx.x * 256 + threadIdx.x;     // 0 .. 28671
    if (i < 4096) {
        int o = i >> 6, k = i & 63;
        g_rt[o * 64 + k] = R[k * 64 + o];
    } else if (i < 4096 + 12288) {
        int j = i - 4096;
        int o = j >> 6, k = j & 63;
        g_wihT[o * 64 + k] = Wih[k * 192 + o];
    } else {
        int j = i - 4096 - 12288;
        int o = j >> 6, k = j & 63;
        g_whhT[o * 64 + k] = Whh[k * 192 + o];
    }
}

// ================= fused factorized message GEMM (k-split) ========================
// msg_e = sum_k h1_ek * (v_e @ W2_k) + v_e @ B2,  v_e = h[src(e)], scatter to agg[dst].
// Grid 256 = 128 edge-blocks x 2 k-halves. Block: 128 edges, 32 chunks (+bias for
// khalf=1), 256 threads (warps 4m x 2n), 2 CTAs/SM. A-side bf16 h1 scaling; mma
// accumulates directly into c. W2 cp.async double-buffered.
//
// dynamic smem layout (bytes):
//   [0, 73728)         w2sm: 2 bufs x [4 chunks][64 o][72 i] bf16
//   [73728, 92160)     vsm:  [128][72] bf16
//   [92160, 109056)    h1b:  [128][33] uint32 (bf16x2 dup, 32 local chunks)
//   [109056, 109568)   dssm: [128] int
//   [109568, 110080)   ssm:  [128] int
#define MSG_SMEM_W2   0
#define MSG_SMEM_V    73728
#define MSG_SMEM_H1   92160
#define MSG_SMEM_DS   109056
#define MSG_SMEM_SS   109568
#define MSG_SMEM_TOTAL 110080
#define W2BUF_BYTES   36864

__device__ __forceinline__ void prefetch_w2(int base_chunk, int nch, int buf,
                                            int tid, uint32_t smem_base) {
    int tasks = nch * 512;                      // nch * 64 rows * 8 segs
    for (int idx = tid; idx < tasks; idx += 256) {
        int cc = idx >> 9;
        int o  = (idx >> 3) & 63;
        int s  = idx & 7;
        const __nv_bfloat16* gp = &g_w2r[((size_t)(base_chunk + cc) * 64 + o) * 64 + s * 8];
        uint32_t sp = smem_base + MSG_SMEM_W2 + buf * W2BUF_BYTES
                      + ((cc * 64 + o) * 72 + s * 8) * 2;
        asm volatile("cp.async.cg.shared.global [%0], [%1], 16;" :: "r"(sp), "l"(gp));
    }
    asm volatile("cp.async.commit_group;" ::: "memory");
}

__global__ __launch_bounds__(256, 2) void msg_gemm(const int* __restrict__ src,
                                                   const int* __restrict__ dst) {
    extern __shared__ char smem[];
    __nv_bfloat16* vsm = (__nv_bfloat16*)(smem + MSG_SMEM_V);
    uint32_t* h1b = (uint32_t*)(smem + MSG_SMEM_H1);
    int* dssm = (int*)(smem + MSG_SMEM_DS);
    int* ssm  = (int*)(smem + MSG_SMEM_SS);
    uint32_t smem_base = (uint32_t)__cvta_generic_to_shared(smem);

    int tid = threadIdx.x;
    int ebid = blockIdx.x & 127;
    int khalf = blockIdx.x >> 7;
    int e0 = ebid * 128;
    int kbase = khalf * 32;

    if (tid < 128) {
        ssm[tid] = src[e0 + tid];
        dssm[tid] = dst[e0 + tid];
    }
    // kick off W2 group 0 into buf 0
    prefetch_w2(kbase, 4, 0, tid, smem_base);
    __syncthreads();                            // ssm visible

    // gather v (bf16)
#pragma unroll
    for (int p = 0; p < 8; p++) {
        int idx = tid + p * 256;                // 2048 tasks: 128 rows x 16 segs
        int row = idx >> 4, seg = idx & 15;
        int s = ssm[row];
        float4 v = *(const float4*)&g_h[(size_t)s * 64 + seg * 4];
        __nv_bfloat162 p0 = __floats2bfloat162_rn(v.x, v.y);
        __nv_bfloat162 p1 = __floats2bfloat162_rn(v.z, v.w);
        uint2 u; u.x = *(uint32_t*)&p0; u.y = *(uint32_t*)&p1;
        *(uint2*)&vsm[row * 72 + seg * 4] = u;
    }
    // gather h1 (bf16x2 dup) for this block's 32 chunks
#pragma unroll
    for (int p = 0; p < 4; p++) {
        int idx = tid + p * 256;                // 1024 tasks: 128 rows x 8 quads
        int row = idx >> 3, q = idx & 7;
        float4 hv = *(const float4*)&g_h1f[(size_t)(e0 + row) * 64 + kbase + q * 4];
        __nv_bfloat16 b0 = __float2bfloat16(hv.x);
        __nv_bfloat16 b1 = __float2bfloat16(hv.y);
        __nv_bfloat16 b2 = __float2bfloat16(hv.z);
        __nv_bfloat16 b3 = __float2bfloat16(hv.w);
        h1b[row * 33 + q * 4 + 0] = ((uint32_t)*(uint16_t*)&b0) * 0x00010001u;
        h1b[row * 33 + q * 4 + 1] = ((uint32_t)*(uint16_t*)&b1) * 0x00010001u;
        h1b[row * 33 + q * 4 + 2] = ((uint32_t)*(uint16_t*)&b2) * 0x00010001u;
        h1b[row * 33 + q * 4 + 3] = ((uint32_t)*(uint16_t*)&b3) * 0x00010001u;
    }
    __syncthreads();

    int w = tid >> 5, lane = tid & 31;
    int warpM = w >> 1, warpN = w & 1;          // 4 m-warps x 2 n-warps
    int rowbase = warpM * 32;
    int g = lane >> 2, t4 = lane & 3;

    // v fragments (persist in registers for all chunks)
    uint32_t vfrag[2][4][4];
#pragma unroll
    for (int mt = 0; mt < 2; mt++)
#pragma unroll
        for (int ks = 0; ks < 4; ks++) {
            int r0 = rowbase + mt * 16 + g;
            int cl = ks * 16 + 2 * t4;
            vfrag[mt][ks][0] = *(const uint32_t*)&vsm[r0 * 72 + cl];
            vfrag[mt][ks][1] = *(const uint32_t*)&vsm[(r0 + 8) * 72 + cl];
            vfrag[mt][ks][2] = *(const uint32_t*)&vsm[r0 * 72 + cl + 8];
            vfrag[mt][ks][3] = *(const uint32_t*)&vsm[(r0 + 8) * 72 + cl + 8];
        }

    float c[2][4][4];
#pragma unroll
    for (int mt = 0; mt < 2; mt++)
#pragma unroll
        for (int ni = 0; ni < 4; ni++)
#pragma unroll
            for (int r = 0; r < 4; r++) c[mt][ni][r] = 0.f;

#pragma unroll 1
    for (int grp = 0; grp < 8; grp++) {
        asm volatile("cp.async.wait_group 0;" ::: "memory");
        __syncthreads();
        int buf = grp & 1;
        if (grp < 7)           prefetch_w2(kbase + (grp + 1) * 4, 4, (grp + 1) & 1, tid, smem_base);
        else if (khalf == 1)   prefetch_w2(64, 1, 0, tid, smem_base);
        const __nv_bfloat16* w2p =
            (const __nv_bfloat16*)(smem + MSG_SMEM_W2 + buf * W2BUF_BYTES);
#pragma unroll 1
        for (int cc = 0; cc < 4; cc++) {
            int kloc = grp * 4 + cc;
            uint32_t hA[2], hB[2];
#pragma unroll
            for (int mt = 0; mt < 2; mt++) {
                int rA = rowbase + mt * 16 + g;
                hA[mt] = h1b[rA * 33 + kloc];
                hB[mt] = h1b[(rA + 8) * 33 + kloc];
            }
#pragma unroll
            for (int ks = 0; ks < 4; ks++) {
                uint32_t b[4][2];
#pragma unroll
                for (int ni = 0; ni < 4; ni++) {
                    int orow = warpN * 32 + ni * 8 + g;
                    int ib = ks * 16 + 2 * t4;
                    b[ni][0] = *(const uint32_t*)&w2p[(cc * 64 + orow) * 72 + ib];
                    b[ni][1] = *(const uint32_t*)&w2p[(cc * 64 + orow) * 72 + ib + 8];
                }
#pragma unroll
                for (int mt = 0; mt < 2; mt++) {
                    uint32_t sa[4];
                    sa[0] = hmul2b(vfrag[mt][ks][0], hA[mt]);
                    sa[1] = hmul2b(vfrag[mt][ks][1], hB[mt]);
                    sa[2] = hmul2b(vfrag[mt][ks][2], hA[mt]);
                    sa[3] = hmul2b(vfrag[mt][ks][3], hB[mt]);
#pragma unroll
                    for (int ni = 0; ni < 4; ni++)
                        mma_bf16(c[mt][ni], sa, b[ni]);
                }
            }
        }
        __syncthreads();
    }

    // bias chunk (k=64, unit coefficient) — only khalf==1, in buf 0
    if (khalf == 1) {
        asm volatile("cp.async.wait_group 0;" ::: "memory");
        __syncthreads();
        const __nv_bfloat16* w2p = (const __nv_bfloat16*)(smem + MSG_SMEM_W2);
#pragma unroll
        for (int ks = 0; ks < 4; ks++) {
            uint32_t b[4][2];
#pragma unroll
            for (int ni = 0; ni < 4; ni++) {
                int orow = warpN * 32 + ni * 8 + g;
                int ib = ks * 16 + 2 * t4;
                b[ni][0] = *(const uint32_t*)&w2p[orow * 72 + ib];
                b[ni][1] = *(const uint32_t*)&w2p[orow * 72 + ib + 8];
            }
#pragma unroll
            for (int mt = 0; mt < 2; mt++)
#pragma unroll
                for (int ni = 0; ni < 4; ni++)
                    mma_bf16(c[mt][ni], vfrag[mt][ks], b[ni]);
        }
    }

    // scatter into agg
#pragma unroll
    for (int mt = 0; mt < 2; mt++)
#pragma unroll
        for (int half = 0; half < 2; half++) {
            int row = rowbase + mt * 16 + g + half * 8;
            int d = dssm[row];
            float* ap = &g_agg[(size_t)d * 64 + warpN * 32];
#pragma unroll
            for (int ni = 0; ni < 4; ni++) {
                atomicAdd(&ap[ni * 8 + 2 * t4],     c[mt][ni][half * 2 + 0]);
                atomicAdd(&ap[ni * 8 + 2 * t4 + 1], c[mt][ni][half * 2 + 1]);
            }
        }
}

// ---------------- tf32 tensor-core NNConv epilogue + GRU (64 nodes/block) ----------
__global__ __launch_bounds__(256) void node_update_tc(
    const float* __restrict__ cbias,
    const float* __restrict__ bih, const float* __restrict__ bhh) {
    __shared__ float hsm[64][68];
    __shared__ float msm[64][68];
    int n0 = blockIdx.x * 64;
    int tid = threadIdx.x;

#pragma unroll
    for (int i = 0; i < 4; i++) {
        int idx = tid + i * 256;
        int row = idx >> 4, c4 = (idx & 15) * 4;
        *(float4*)&hsm[row][c4] = *(const float4*)&g_h[(size_t)(n0 + row) * 64 + c4];
    }
    __syncthreads();

    int w = tid >> 5, lane = tid & 31;
    int g = lane >> 2, t4 = lane & 3;
    int c0 = w * 8 + 2 * t4;

    float accB[4][4] = {};
#pragma unroll
    for (int ks = 0; ks < 8; ks++) {
        int k0 = ks * 8;
        uint32_t rb[2];
        int nrow = w * 8 + g;
        rb[0] = f2tf32(g_rt[nrow * 64 + k0 + t4]);
        rb[1] = f2tf32(g_rt[nrow * 64 + k0 + t4 + 4]);
#pragma unroll
        for (int mt = 0; mt < 4; mt++) {
            int r0 = mt * 16 + g;
            uint32_t a[4];
            a[0] = f2tf32(hsm[r0][k0 + t4]);
            a[1] = f2tf32(hsm[r0 + 8][k0 + t4]);
            a[2] = f2tf32(hsm[r0][k0 + t4 + 4]);
            a[3] = f2tf32(hsm[r0 + 8][k0 + t4 + 4]);
            mma_tf32(accB[mt], a, rb);
        }
    }
    {
        float2 cb = *(const float2*)&cbias[c0];
#pragma unroll
        for (int mt = 0; mt < 4; mt++) {
#pragma unroll
            for (int half = 0; half < 2; half++) {
                int row = mt * 16 + g + half * 8;
                int node = n0 + row;
                float inv = g_deg[node];
                float2 ag = *(float2*)&g_agg[(size_t)node * 64 + c0];
                *(float2*)&g_agg[(size_t)node * 64 + c0] = make_float2(0.f, 0.f);
                msm[row][c0]     = lrelu(ag.x * inv + accB[mt][half * 2 + 0] + cb.x);
                msm[row][c0 + 1] = lrelu(ag.y * inv + accB[mt][half * 2 + 1] + cb.y);
            }
        }
    }
    __syncthreads();

    float accI[4][3][4] = {};
    float accH[4][3][4] = {};
#pragma unroll
    for (int ks = 0; ks < 8; ks++) {
        int k0 = ks * 8;
        uint32_t bi[3][2], bh[3][2];
#pragma unroll
        for (int j = 0; j < 3; j++) {
            int nrow = j * 64 + w * 8 + g;
            bi[j][0] = f2tf32(g_wihT[nrow * 64 + k0 + t4]);
            bi[j][1] = f2tf32(g_wihT[nrow * 64 + k0 + t4 + 4]);
            bh[j][0] = f2tf32(g_whhT[nrow * 64 + k0 + t4]);
            bh[j][1] = f2tf32(g_whhT[nrow * 64 + k0 + t4 + 4]);
        }
#pragma unroll
        for (int mt = 0; mt < 4; mt++) {
            int r0 = mt * 16 + g;
            uint32_t am[4], ah[4];
            am[0] = f2tf32(msm[r0][k0 + t4]);
            am[1] = f2tf32(msm[r0 + 8][k0 + t4]);
            am[2] = f2tf32(msm[r0][k0 + t4 + 4]);
            am[3] = f2tf32(msm[r0 + 8][k0 + t4 + 4]);
            ah[0] = f2tf32(hsm[r0][k0 + t4]);
            ah[1] = f2tf32(hsm[r0 + 8][k0 + t4]);
            ah[2] = f2tf32(hsm[r0][k0 + t4 + 4]);
            ah[3] = f2tf32(hsm[r0 + 8][k0 + t4 + 4]);
#pragma unroll
            for (int j = 0; j < 3; j++) {
                mma_tf32(accI[mt][j], am, bi[j]);
                mma_tf32(accH[mt][j], ah, bh[j]);
            }
        }
    }

    float2 b_ir = *(const float2*)&bih[c0];
    float2 b_iz = *(const float2*)&bih[64 + c0];
    float2 b_in = *(const float2*)&bih[128 + c0];
    float2 b_hr = *(const float2*)&bhh[c0];
    float2 b_hz = *(const float2*)&bhh[64 + c0];
    float2 b_hn = *(const float2*)&bhh[128 + c0];
#pragma unroll
    for (int mt = 0; mt < 4; mt++) {
#pragma unroll
        for (int half = 0; half < 2; half++) {
            int row = mt * 16 + g + half * 8;
            int node = n0 + row;
            int o = half * 2;
            float2 hold = make_float2(hsm[row][c0], hsm[row][c0 + 1]);
            float rx = sigm(accI[mt][0][o] + b_ir.x + accH[mt][0][o] + b_hr.x);
            float zx = sigm(accI[mt][1][o] + b_iz.x + accH[mt][1][o] + b_hz.x);
            float nx = tanhf(accI[mt][2][o] + b_in.x + rx * (accH[mt][2][o] + b_hn.x));
            float ry = sigm(accI[mt][0][o + 1] + b_ir.y + accH[mt][0][o + 1] + b_hr.y);
            float zy = sigm(accI[mt][1][o + 1] + b_iz.y + accH[mt][1][o + 1] + b_hz.y);
            float ny = tanhf(accI[mt][2][o + 1] + b_in.y + ry * (accH[mt][2][o + 1] + b_hn.y));
            float2 hn;
            hn.x = (1.f - zx) * nx + zx * hold.x;
            hn.y = (1.f - zy) * ny + zy * hold.y;
            *(float2*)&g_h[(size_t)node * 64 + c0] = hn;
        }
    }
}

// ---------------- stem head ----------------
__global__ __launch_bounds__(128) void stem_kernel(const int* __restrict__ idx,
                                                   const float* __restrict__ W1, const float* __restrict__ b1,
                                                   const float* __restrict__ W2, const float* __restrict__ b2,
                                                   float* __restrict__ outp) {
    __shared__ float row[64], hid[64];
    int s = blockIdx.x, t = threadIdx.x;
    int atom = idx[s];
    if (t < 64) row[t] = g_h[(size_t)atom * 64 + t];
    __syncthreads();
    if (t < 64) {
        float acc = b1[t];
#pragma unroll
        for (int i = 0; i < 64; i++) acc += row[i] * W1[i * 64 + t];
        hid[t] = lrelu(acc);
    }
    __syncthreads();
    for (int o = t; o < NUM_OUT; o += 128) {
        float acc = b2[o];
#pragma unroll
        for (int i = 0; i < 64; i++) acc += hid[i] * W2[i * NUM_OUT + o];
        outp[512 + (size_t)s * NUM_OUT + o] = acc;
    }
}

// ---------------- jbond head ----------------
__global__ __launch_bounds__(128) void jbond_kernel(const int* __restrict__ idx,
                                                    const float* __restrict__ W1, const float* __restrict__ b1,
                                                    const float* __restrict__ w2, const float* __restrict__ b2,
                                                    float* __restrict__ outp) {
    __shared__ float row[2][64];
    __shared__ float warpsum[4];
    int jb = blockIdx.x, t = threadIdx.x;
    int a = t >> 6, tt = t & 63;
    int atom = idx[jb * 2 + a];
    row[a][tt] = g_h[(size_t)atom * 64 + tt];
    __syncthreads();
    float acc = b1[tt];
#pragma unroll
    for (int i = 0; i < 64; i++) acc += row[a][i] * W1[i * 64 + tt];
    float p = lrelu(acc) * w2[tt];
#pragma unroll
    for (int off = 16; off; off >>= 1) p += __shfl_xor_sync(0xffffffffu, p, off);
    if ((t & 31) == 0) warpsum[t >> 5] = p;
    __syncthreads();
    if (t == 0) {
        float p0 = warpsum[0] + warpsum[1] + b2[0];
        float p1 = warpsum[2] + warpsum[3] + b2[0];
        outp[512 + (size_t)N_STEMS * NUM_OUT + jb] = 0.5f * (p0 + p1);
    }
}

// ---------------- Set2Set q (bias-only; identical for all graphs) ----------------
__global__ void s2s_q_kernel(const float* __restrict__ bih, const float* __restrict__ bhh) {
    int d = threadIdx.x;
    float bi = bih[d]       + bhh[d];
    float bg = bih[128 + d] + bhh[128 + d];
    float bo = bih[192 + d] + bhh[192 + d];
    float c = sigm(bi) * tanhf(bg);
    g_q[d] = sigm(bo) * tanhf(c);
}

// ---------------- per-graph attention pool + lin_out ----------------
__global__ __launch_bounds__(128) void pool_kernel(const int* __restrict__ batch,
                                                   const float* __restrict__ W, const float* __restrict__ bias,
                                                   float* __restrict__ outp) {
    __shared__ int s_lo, s_hi;
    __shared__ float s_max[4], s_ws[4], s_pool[4][64], s_r[64];
    int b = blockIdx.x, t = threadIdx.x;
    if (t == 0) {
        int lo = 0, hi = N_NODES;
        while (lo < hi) { int m = (lo + hi) >> 1; if (batch[m] < b) lo = m + 1; else hi = m; }
        s_lo = lo;
        int lo2 = lo, hi2 = N_NODES;
        while (lo2 < hi2) { int m = (lo2 + hi2) >> 1; if (batch[m] < b + 1) lo2 = m + 1; else hi2 = m; }
        s_hi = lo2;
    }
    __syncthreads();
    int lo = s_lo, hi = s_hi;
    int warp = t >> 5, lane = t & 31;
    float q0 = g_q[lane], q1 = g_q[32 + lane];
    float lmax = -3.4e38f;
    for (int n = lo + warp; n < hi; n += 4) {
        float v = g_h[(size_t)n * 64 + lane] * q0 + g_h[(size_t)n * 64 + 32 + lane] * q1;
#pragma unroll
        for (int off = 16; off; off >>= 1) v += __shfl_xor_sync(0xffffffffu, v, off);
        lmax = fmaxf(lmax, v);
    }
    if (lane == 0) s_max[warp] = lmax;
    __syncthreads();
    float emax = fmaxf(fmaxf(s_max[0], s_max[1]), fmaxf(s_max[2], s_max[3]));
    float p0 = 0.f, p1 = 0.f, ws = 0.f;
    for (int n = lo + warp; n < hi; n += 4) {
        float h0 = g_h[(size_t)n * 64 + lane], h1v = g_h[(size_t)n * 64 + 32 + lane];
        float v = h0 * q0 + h1v * q1;
#pragma unroll
        for (int off = 16; off; off >>= 1) v += __shfl_xor_sync(0xffffffffu, v, off);
        float c = expf(v - emax);
        p0 += c * h0; p1 += c * h1v; ws += c;
    }
    s_pool[warp][lane] = p0; s_pool[warp][32 + lane] = p1;
    if (lane == 0) s_ws[warp] = ws;
    __syncthreads();
    if (t < 64) {
        float ps = s_pool[0][t] + s_pool[1][t] + s_pool[2][t] + s_pool[3][t];
        float wtot = s_ws[0] + s_ws[1] + s_ws[2] + s_ws[3];
        s_r[t] = (wtot > 0.f) ? ps / wtot : 0.f;
    }
    __syncthreads();
    if (t < 2) {
        float acc = bias[t];
        for (int d = 0; d < 64; d++)
            acc += g_q[d] * W[d * 2 + t] + s_r[d] * W[(64 + d) * 2 + t];
        outp[b * 2 + t] = acc;
    }
}

// ---------------- launch ----------------
extern "C" void kernel_launch(void* const* d_in, const int* in_sizes, int n_in,
                              void* d_out, int out_size) {
    const float* x          = (const float*)d_in[0];
    const float* edge_attr  = (const float*)d_in[1];
    const int*   edge_index = (const int*)  d_in[2];
    const int*   batch      = (const int*)  d_in[3];
    const int*   stem_idx   = (const int*)  d_in[4];
    const int*   jbond_idx  = (const int*)  d_in[5];
    const float* lin0_w   = (const float*)d_in[6];
    const float* lin0_b   = (const float*)d_in[7];
    const float* net_w1   = (const float*)d_in[8];
    const float* net_b1   = (const float*)d_in[9];
    const float* net_w2   = (const float*)d_in[10];
    const float* net_b2   = (const float*)d_in[11];
    const float* conv_root= (const float*)d_in[12];
    const float* conv_bias= (const float*)d_in[13];
    const float* gru_w_ih = (const float*)d_in[14];
    const float* gru_w_hh = (const float*)d_in[15];
    const float* gru_b_ih = (const float*)d_in[16];
    const float* gru_b_hh = (const float*)d_in[17];
    const float* n2s_w1   = (const float*)d_in[18];
    const float* n2s_b1   = (const float*)d_in[19];
    const float* n2s_w2   = (const float*)d_in[20];
    const float* n2s_b2   = (const float*)d_in[21];
    const float* n2j_w1   = (const float*)d_in[22];
    const float* n2j_b1   = (const float*)d_in[23];
    const float* n2j_w2   = (const float*)d_in[24];
    const float* n2j_b2   = (const float*)d_in[25];
    const float* s2s_b_ih = (const float*)d_in[28];
    const float* s2s_b_hh = (const float*)d_in[29];
    const float* lin_out_w= (const float*)d_in[30];
    const float* lin_out_b= (const float*)d_in[31];
    float* out = (float*)d_out;

    const int* src = edge_index;             // edge_index[0]
    const int* dst = edge_index + N_EDGES;   // edge_index[1]

    cudaFuncSetAttribute(msg_gemm, cudaFuncAttributeMaxDynamicSharedMemorySize,
                         MSG_SMEM_TOTAL);

    zero_deg_kernel<<<N_NODES / 256, 256>>>();
    deg_kernel<<<(N_EDGES + 255) / 256, 256>>>(dst);
    invdeg_kernel<<<N_NODES / 256, 256>>>();
    zero_agg_kernel<<<N_NODES * DIM / 4 / 256, 256>>>();
    lin0_kernel<<<N_NODES * DIM / 256, 256>>>(x, lin0_w, lin0_b);
    h1_kernel<<<N_EDGES * DIM / 256, 256>>>(edge_attr, net_w1, net_b1);
    w2r_kernel<<<(65 * 4096 + 255) / 256, 256>>>(net_w2, net_b2);
    prep_weights_kernel<<<112, 256>>>(conv_root, gru_w_ih, gru_w_hh);

    for (int it = 0; it < 6; it++) {
        msg_gemm<<<256, 256, MSG_SMEM_TOTAL>>>(src, dst);
        node_update_tc<<<N_NODES / 64, 256>>>(conv_bias, gru_b_ih, gru_b_hh);
    }

    stem_kernel<<<N_STEMS, 128>>>(stem_idx, n2s_w1, n2s_b1, n2s_w2, n2s_b2, out);
    jbond_kernel<<<N_JBONDS, 128>>>(jbond_idx, n2j_w1, n2j_b1, n2j_w2, n2j_b2, out);
    s2s_q_kernel<<<1, 64>>>(s2s_b_ih, s2s_b_hh);
    pool_kernel<<<N_GRAPHS, 128>>>(batch, lin_out_w, lin_out_b, out);
}